// round 14
// baseline (speedup 1.0000x reference)
#include <cuda_runtime.h>
#include <cuda_bf16.h>
#include <cstdint>

// Chunked-parallel scan of:  s = sigmoid(10*(s + (Wx+b)_t - 0.5)),  pred_t = x_t . s
// Run in t = 2s-1 domain:  t' = tanh(2.5 t + 5(Wx+b)),
// pred = 0.5*(x.t) + 0.5*(x0+x1+x2).  One MUFU.TANH per component per step.
//
// R13 (= R12 resubmit; prior round was an infra failure, kernel never ran):
// R11's flat shared warp window (780-f4 contiguous span per warp,
// slot = span*25 + w, conflict-free at lane stride 25) with:
//  - TPB=64 (2 warps/block), 2048 blocks, 25.4KB static smem -> 8 blocks/SM
//    (finer scheduling stagger, same 16 warps/SM)
//  - 3 commit groups: G0 = warmup region (w 0..11, spans 0..32),
//    G1 = main w 12..17, G2 = main w 18..23; progressive drain so the first
//    8 main steps run while G2 is still in flight.
// Preds stashed in consumed own-lane slots, stored fully coalesced.

static constexpr int CHUNK  = 32;               // steps per thread (24 f4)
static constexpr int WM     = 16;               // warmup steps (12 f4)
static constexpr int TPB    = 64;               // 2 warps
static constexpr int WPB    = TPB / 32;
static constexpr int G0N    = 33 * 12;          // 396 f4 (w in [0,12), span 0..32)
static constexpr int WSLICE = 812;              // max slot 32*25+11=811, +1

__device__ __forceinline__ float tanhapx(float z) {
    float r; asm("tanh.approx.f32 %0, %1;" : "=f"(r) : "f"(z)); return r;
}
__device__ __forceinline__ void cp16(unsigned int dst, const void* src) {
    asm volatile("cp.async.cg.shared.global [%0], [%1], 16;" :: "r"(dst), "l"(src));
}

__global__ void __launch_bounds__(TPB, 8)
updater_kernel(const float* __restrict__ x,
               const float* __restrict__ Wg,
               const float* __restrict__ bg,
               const float* __restrict__ net0,
               float* __restrict__ out)
{
    __shared__ float4 sm[WPB * WSLICE];         // 25984 B static

    const int lane = threadIdx.x & 31;
    const int wid  = threadIdx.x >> 5;
    const int w0c  = blockIdx.x * TPB + wid * 32;       // warp's first chunk
    const bool first = (blockIdx.x == 0) && (wid == 0) && (lane == 0);

    // u5 = 5*(W x + b)
    const float W00 = 5.f*Wg[0], W01 = 5.f*Wg[1], W02 = 5.f*Wg[2];
    const float W10 = 5.f*Wg[3], W11 = 5.f*Wg[4], W12 = 5.f*Wg[5];
    const float W20 = 5.f*Wg[6], W21 = 5.f*Wg[7], W22 = 5.f*Wg[8];
    const float c0 = 5.f*bg[0], c1 = 5.f*bg[1], c2 = 5.f*bg[2];

    const float4* __restrict__ xf4 = reinterpret_cast<const float4*>(x);
    float4* __restrict__ of4 = reinterpret_cast<float4*>(out);

    float4* xw = sm + wid * WSLICE;
    const unsigned int sbase = (unsigned int)__cvta_generic_to_shared(xw);
    const long gbase = (long)w0c * 24 - 12;             // window start (global f4)

    // ---- G0: warmup-phase data, w in [0,12), spans 0..32 (396 f4) ----
    #pragma unroll
    for (int l = 0; l < 13; ++l) {
        int i = lane + 32 * l;                  // 0..415
        if (i < G0N) {
            int span = i / 12, w = i - span * 12;
            long g = gbase + span * 24 + w;
            if (g < 0) g = 0;                   // only global chunk 0's discarded warmup
            cp16(sbase + (unsigned int)(span * 25 + w) * 16u, xf4 + g);
        }
    }
    asm volatile("cp.async.commit_group;");

    // ---- G1: main w in [12,18), spans 0..31 (192 f4) ----
    #pragma unroll
    for (int l = 0; l < 6; ++l) {
        int i = lane + 32 * l;                  // 0..191
        int span = i / 6, w = 12 + (i - span * 6);
        cp16(sbase + (unsigned int)(span * 25 + w) * 16u, xf4 + gbase + span * 24 + w);
    }
    asm volatile("cp.async.commit_group;");

    // ---- G2: main w in [18,24), spans 0..31 (192 f4) ----
    #pragma unroll
    for (int l = 0; l < 6; ++l) {
        int i = lane + 32 * l;
        int span = i / 6, w = 18 + (i - span * 6);
        cp16(sbase + (unsigned int)(span * 25 + w) * 16u, xf4 + gbase + span * 24 + w);
    }
    asm volatile("cp.async.commit_group;");

    float t0 = 0.f, t1 = 0.f, t2 = 0.f;         // midpoint seed (s = 0.5)
    float4* my = xw + lane * 25;                // lane base; j<24: slot=j, j>=24: slot=j+1

    // ---- warmup: 16 steps, j = 0..11 (G0) ----
    asm volatile("cp.async.wait_group 2;");
    __syncwarp();
    #pragma unroll
    for (int g = 0; g < WM / 4; ++g) {
        float4 p = my[3*g], q = my[3*g+1], r = my[3*g+2];
        auto wstep = [&](float X0, float X1, float X2) {
            float u0 = fmaf(W00, X0, fmaf(W01, X1, fmaf(W02, X2, c0)));
            float u1 = fmaf(W10, X0, fmaf(W11, X1, fmaf(W12, X2, c1)));
            float u2 = fmaf(W20, X0, fmaf(W21, X1, fmaf(W22, X2, c2)));
            t0 = tanhapx(fmaf(2.5f, t0, u0));
            t1 = tanhapx(fmaf(2.5f, t1, u1));
            t2 = tanhapx(fmaf(2.5f, t2, u2));
        };
        wstep(p.x, p.y, p.z);
        wstep(p.w, q.x, q.y);
        wstep(q.z, q.w, r.x);
        wstep(r.y, r.z, r.w);
    }
    if (first) {
        t0 = fmaf(2.f, net0[0], -1.f);
        t1 = fmaf(2.f, net0[1], -1.f);
        t2 = fmaf(2.f, net0[2], -1.f);
    }

    auto mstep = [&](float X0, float X1, float X2) -> float {
        float u0 = fmaf(W00, X0, fmaf(W01, X1, fmaf(W02, X2, c0)));
        float u1 = fmaf(W10, X0, fmaf(W11, X1, fmaf(W12, X2, c1)));
        float u2 = fmaf(W20, X0, fmaf(W21, X1, fmaf(W22, X2, c2)));
        t0 = tanhapx(fmaf(2.5f, t0, u0));
        t1 = tanhapx(fmaf(2.5f, t1, u1));
        t2 = tanhapx(fmaf(2.5f, t2, u2));
        float h = fmaf(0.5f, X2, fmaf(0.5f, X1, 0.5f * X0));
        float d = fmaf(X0, t0, fmaf(X1, t1, X2 * t2));
        return fmaf(0.5f, d, h);
    };

    // ---- main steps 1..8: j = 12..17 (G1 only) ----
    asm volatile("cp.async.wait_group 1;");
    __syncwarp();
    #pragma unroll
    for (int g = 0; g < 2; ++g) {
        float4 p = my[12 + 3*g], q = my[13 + 3*g], r = my[14 + 3*g];
        float4 res;
        res.x = mstep(p.x, p.y, p.z);
        res.y = mstep(p.w, q.x, q.y);
        res.z = mstep(q.z, q.w, r.x);
        res.w = mstep(r.y, r.z, r.w);
        my[12 + g] = res;                       // consumed G1 slot; own-lane only
    }

    // ---- main steps 9..32: j = 18..35 (G2 + already-waited G0 of lane+1) ----
    asm volatile("cp.async.wait_group 0;");
    __syncwarp();
    #pragma unroll
    for (int g = 2; g < 8; ++g) {
        int j0 = 12 + 3*g, j1 = 13 + 3*g, j2 = 14 + 3*g;
        float4 p = my[j0 + (j0 >= 24 ? 1 : 0)];
        float4 q = my[j1 + (j1 >= 24 ? 1 : 0)];
        float4 r = my[j2 + (j2 >= 24 ? 1 : 0)];
        float4 res;
        res.x = mstep(p.x, p.y, p.z);
        res.y = mstep(p.w, q.x, q.y);
        res.z = mstep(q.z, q.w, r.x);
        res.w = mstep(r.y, r.z, r.w);
        my[12 + g] = res;                       // write after all reads of this slot
    }
    __syncwarp();

    // ---- coalesced store: 32 chunks x 8 pred f4 = 512B per warp-instruction ----
    #pragma unroll
    for (int l = 0; l < 8; ++l) {
        int f   = lane + 32 * l;                // 0..255
        int seg = f >> 3;
        int off = f & 7;
        of4[(long)(w0c + seg) * 8 + off] = xw[seg * 25 + 12 + off];
    }
}

extern "C" void kernel_launch(void* const* d_in, const int* in_sizes, int n_in,
                              void* d_out, int out_size)
{
    const float* x    = (const float*)d_in[0];
    const float* W    = (const float*)d_in[1];
    const float* b    = (const float*)d_in[2];
    const float* net0 = (const float*)d_in[3];
    float* out = (float*)d_out;

    int n       = in_sizes[0] / 3;     // B = 4194304
    int nchunks = n / CHUNK;           // 131072
    int blocks  = nchunks / TPB;       // 2048
    updater_kernel<<<blocks, TPB>>>(x, W, b, net0, out);
}

// round 15
// speedup vs baseline: 1.0021x; 1.0021x over previous
#include <cuda_runtime.h>
#include <cuda_bf16.h>
#include <cstdint>

// Chunked-parallel scan of:  s = sigmoid(10*(s + (Wx+b)_t - 0.5)),  pred_t = x_t . s
// Run in t = 2s-1 domain:  t' = tanh(2.5 t + 5(Wx+b)),
// pred = 0.5*(x.t) + 0.5*(x0+x1+x2).  One MUFU.TANH per component per step.
//
// R15: chained windows + pipelined loads. Each lane owns 128 CONSECUTIVE steps
// (4 windows of 32); state chains across windows so warmup (16 steps) runs once
// per 128 steps (amplification 1.5x -> 1.125x, steps -25%). Window loads are
// double-buffered via cp.async commit groups: window i+1 is issued before
// computing window i, hiding DRAM latency after the first window.
// One warp per block, 32.3KB smem -> 7 blocks/SM, grid 1024 = single wave.

static constexpr int WSTEPS = 32;               // steps per window (24 f4 per lane)
static constexpr int NW     = 4;                // windows per lane (128 steps)
static constexpr int WM     = 16;               // warmup steps (12 f4)
static constexpr int TPB    = 32;               // one warp per block
static constexpr int WBUFN  = 32 * 13;          // warmup buffer (pitch 13)
static constexpr int WINN   = 32 * 25;          // window buffer (pitch 25)

__device__ __forceinline__ float tanhapx(float z) {
    float r; asm("tanh.approx.f32 %0, %1;" : "=f"(r) : "f"(z)); return r;
}
__device__ __forceinline__ void cp16(unsigned int dst, const void* src) {
    asm volatile("cp.async.cg.shared.global [%0], [%1], 16;" :: "r"(dst), "l"(src));
}

__global__ void __launch_bounds__(TPB, 7)
updater_kernel(const float* __restrict__ x,
               const float* __restrict__ Wg,
               const float* __restrict__ bg,
               const float* __restrict__ net0,
               float* __restrict__ out)
{
    __shared__ float4 sm[WBUFN + 2 * WINN];     // 416 + 1600 f4 = 32256 B

    const int lane = threadIdx.x;               // 0..31
    const long wb  = blockIdx.x;                // warp id = block id (1024 total)
    const bool first = (wb == 0) && (lane == 0);

    // u5 = 5*(W x + b)
    const float W00 = 5.f*Wg[0], W01 = 5.f*Wg[1], W02 = 5.f*Wg[2];
    const float W10 = 5.f*Wg[3], W11 = 5.f*Wg[4], W12 = 5.f*Wg[5];
    const float W20 = 5.f*Wg[6], W21 = 5.f*Wg[7], W22 = 5.f*Wg[8];
    const float c0 = 5.f*bg[0], c1 = 5.f*bg[1], c2 = 5.f*bg[2];

    const float4* __restrict__ xf4 = reinterpret_cast<const float4*>(x);
    float4* __restrict__ of4 = reinterpret_cast<float4*>(out);

    const unsigned int swb  = (unsigned int)__cvta_generic_to_shared(sm);
    const unsigned int swin = swb + WBUFN * 16u;
    const long gbase = wb * 3072;               // warp's span start (f4); 4096 steps

    // ---- issue warmup preamble: lane seg's 12 f4 ending at its first step ----
    #pragma unroll
    for (int l = 0; l < 12; ++l) {
        int i = lane + 32 * l;                  // 0..383
        int seg = i / 12, off = i - seg * 12;
        long g = gbase + seg * 96 - 12 + off;
        if (g < 0) g = 0;                       // only warp 0 seg 0 (discarded)
        cp16(swb + (unsigned int)(seg * 13 + off) * 16u, xf4 + g);
    }
    asm volatile("cp.async.commit_group;");

    // ---- issue a window's loads: 32 segments x 24 f4 (stride 96) ----
    auto issue_win = [&](int wi) {
        unsigned int dbuf = swin + (unsigned int)((wi & 1) * WINN) * 16u;
        #pragma unroll
        for (int l = 0; l < 24; ++l) {
            int i = lane + 32 * l;              // 0..767
            int seg = i / 24, off = i - seg * 24;
            cp16(dbuf + (unsigned int)(seg * 25 + off) * 16u,
                 xf4 + gbase + seg * 96 + wi * 24 + off);
        }
        asm volatile("cp.async.commit_group;");
    };

    issue_win(0);

    float t0 = 0.f, t1 = 0.f, t2 = 0.f;         // midpoint seed (s = 0.5)

    // ---- warmup: 16 steps from wbuf (window 0's loads still in flight) ----
    asm volatile("cp.async.wait_group 1;");
    __syncwarp();
    {
        const float4* myw = sm + lane * 13;
        #pragma unroll
        for (int g = 0; g < WM / 4; ++g) {
            float4 p = myw[3*g], q = myw[3*g+1], r = myw[3*g+2];
            auto wstep = [&](float X0, float X1, float X2) {
                float u0 = fmaf(W00, X0, fmaf(W01, X1, fmaf(W02, X2, c0)));
                float u1 = fmaf(W10, X0, fmaf(W11, X1, fmaf(W12, X2, c1)));
                float u2 = fmaf(W20, X0, fmaf(W21, X1, fmaf(W22, X2, c2)));
                t0 = tanhapx(fmaf(2.5f, t0, u0));
                t1 = tanhapx(fmaf(2.5f, t1, u1));
                t2 = tanhapx(fmaf(2.5f, t2, u2));
            };
            wstep(p.x, p.y, p.z);
            wstep(p.w, q.x, q.y);
            wstep(q.z, q.w, r.x);
            wstep(r.y, r.z, r.w);
        }
    }
    if (first) {
        t0 = fmaf(2.f, net0[0], -1.f);
        t1 = fmaf(2.f, net0[1], -1.f);
        t2 = fmaf(2.f, net0[2], -1.f);
    }

    auto mstep = [&](float X0, float X1, float X2) -> float {
        float u0 = fmaf(W00, X0, fmaf(W01, X1, fmaf(W02, X2, c0)));
        float u1 = fmaf(W10, X0, fmaf(W11, X1, fmaf(W12, X2, c1)));
        float u2 = fmaf(W20, X0, fmaf(W21, X1, fmaf(W22, X2, c2)));
        t0 = tanhapx(fmaf(2.5f, t0, u0));
        t1 = tanhapx(fmaf(2.5f, t1, u1));
        t2 = tanhapx(fmaf(2.5f, t2, u2));
        float h = fmaf(0.5f, X2, fmaf(0.5f, X1, 0.5f * X0));
        float d = fmaf(X0, t0, fmaf(X1, t1, X2 * t2));
        return fmaf(0.5f, d, h);
    };

    // ---- pipelined window loop: state chains across windows ----
    #pragma unroll
    for (int wi = 0; wi < NW; ++wi) {
        if (wi + 1 < NW) issue_win(wi + 1);     // prefetch next while this computes
        if (wi + 1 < NW) { asm volatile("cp.async.wait_group 1;"); }
        else             { asm volatile("cp.async.wait_group 0;"); }
        __syncwarp();

        float4* buf = sm + WBUFN + (wi & 1) * WINN;
        float4* my  = buf + lane * 25;

        #pragma unroll
        for (int g = 0; g < 8; ++g) {
            float4 p = my[3*g], q = my[3*g+1], r = my[3*g+2];
            float4 res;
            res.x = mstep(p.x, p.y, p.z);
            res.y = mstep(p.w, q.x, q.y);
            res.z = mstep(q.z, q.w, r.x);
            res.w = mstep(r.y, r.z, r.w);
            my[g] = res;    // stash in consumed slot g (read in group g/3 <= g)
        }
        __syncwarp();       // all lanes' preds visible

        // coalesced store: 256 f4, 4x128B runs per warp-instruction
        #pragma unroll
        for (int l = 0; l < 8; ++l) {
            int i = lane + 32 * l;              // 0..255
            int seg = i >> 3, off = i & 7;
            of4[wb * 1024 + seg * 32 + wi * 8 + off] = buf[seg * 25 + off];
        }
        __syncwarp();       // stores read before next iter's cp.async reuses this buffer
    }
}

extern "C" void kernel_launch(void* const* d_in, const int* in_sizes, int n_in,
                              void* d_out, int out_size)
{
    const float* x    = (const float*)d_in[0];
    const float* W    = (const float*)d_in[1];
    const float* b    = (const float*)d_in[2];
    const float* net0 = (const float*)d_in[3];
    float* out = (float*)d_out;

    int n      = in_sizes[0] / 3;               // B = 4194304
    int blocks = n / (32 * WSTEPS * NW);        // 1024 warps, one per block
    updater_kernel<<<blocks, TPB>>>(x, W, b, net0, out);
}